// round 4
// baseline (speedup 1.0000x reference)
#include <cuda_runtime.h>
#include <cstdint>

#define B_  4
#define N_  2048
#define D_  128
#define TM  128
#define TN  64

// smem layout (bytes)
#define SM_SQI 0
#define SM_SQJ 512
#define SM_A   1024
#define SM_B   (1024 + 65536)
#define SM_TOTAL (1024 + 65536 + 32768)

__device__ float g_sq[B_ * N_];

__global__ void sq_kernel(const float* __restrict__ x) {
    int r = blockIdx.x * blockDim.x + threadIdx.x;
    const float4* p = (const float4*)(x + (size_t)r * D_);
    float s = 0.f;
#pragma unroll
    for (int t = 0; t < D_ / 4; t++) {
        float4 v = p[t];
        s += v.x * v.x + v.y * v.y + v.z * v.z + v.w * v.w;
    }
    g_sq[r] = s;
}

__global__ __launch_bounds__(256, 2) void edm_mma_kernel(const float* __restrict__ x,
                                                         float* __restrict__ out) {
    extern __shared__ char smem[];
    const int tid = threadIdx.x;
    const int wid = tid >> 5;
    const int lane = tid & 31;
    const int g  = lane >> 2;   // 0..7
    const int cc = lane & 3;    // 0..3

    const int b  = blockIdx.z;
    const int i0 = blockIdx.y * TM;
    const int j0 = blockIdx.x * TN;
    const float* xb = x + (size_t)b * N_ * D_;

    // ---- load phase: pair-interleaved, XOR-swizzled smem tiles ----
    // slot s = 4*kbi + c holds (x[8*kbi+c], x[8*kbi+c+4]); phys = s ^ ((r&3)<<2)
    {
        const int bb = tid & 3;          // -> r low bits
        const int aa = (tid >> 2) & 3;   // -> kbi low bits
        const int rmid = (tid >> 4);     // 0..15
        // A tile: 128 rows
#pragma unroll
        for (int iter = 0; iter < 8; iter++) {
            int kbi = aa | ((iter & 3) << 2);                 // 0..15
            int r   = bb | (rmid << 2) | ((iter >> 2) << 6);  // 0..127
            const float4* pA = (const float4*)(xb + (size_t)(i0 + r) * D_ + kbi * 8);
            float4 v0 = pA[0], v1 = pA[1];
            float va[8] = {v0.x, v0.y, v0.z, v0.w, v1.x, v1.y, v1.z, v1.w};
            char* rowA = smem + SM_A + r * 512;
            int x4 = (r & 3) << 2;
#pragma unroll
            for (int j = 0; j < 4; j++) {
                int c = (bb + j) & 3;
                int phys = (4 * kbi + c) ^ x4;
                *(float2*)(rowA + phys * 8) = make_float2(va[c], va[c + 4]);
            }
        }
        // B tile: 64 rows
#pragma unroll
        for (int iter = 0; iter < 4; iter++) {
            int kbi = aa | (iter << 2);        // 0..15
            int r   = bb | (rmid << 2);        // 0..63
            const float4* pB = (const float4*)(xb + (size_t)(j0 + r) * D_ + kbi * 8);
            float4 w0 = pB[0], w1 = pB[1];
            float wa[8] = {w0.x, w0.y, w0.z, w0.w, w1.x, w1.y, w1.z, w1.w};
            char* rowB = smem + SM_B + r * 512;
            int x4 = (r & 3) << 2;
#pragma unroll
            for (int j = 0; j < 4; j++) {
                int c = (bb + j) & 3;
                int phys = (4 * kbi + c) ^ x4;
                *(float2*)(rowB + phys * 8) = make_float2(wa[c], wa[c + 4]);
            }
        }
        if (tid < 128)      ((float*)(smem + SM_SQI))[tid]       = g_sq[b * N_ + i0 + tid];
        else if (tid < 192) ((float*)(smem + SM_SQJ))[tid - 128] = g_sq[b * N_ + j0 + tid - 128];
    }
    __syncthreads();

    // ---- mainloop: warp tile 32x32, m16n8k8 tf32 ----
    const int wm = (wid & 3) * 32;    // 0,32,64,96
    const int wn = (wid >> 2) * 32;   // 0,32

    float acc[2][4][4];
#pragma unroll
    for (int mt = 0; mt < 2; mt++)
#pragma unroll
        for (int nt = 0; nt < 4; nt++)
#pragma unroll
            for (int e = 0; e < 4; e++) acc[mt][nt][e] = 0.f;

    const int gx4 = (g & 3) << 2;
#pragma unroll
    for (int kst = 0; kst < 16; kst++) {
        const int phys = (4 * kst + cc) ^ gx4;
        uint32_t a[2][4], bfr[4][2];
#pragma unroll
        for (int mt = 0; mt < 2; mt++) {
            int r0 = wm + 16 * mt + g;
            float2 a02 = *(float2*)(smem + SM_A + r0 * 512 + phys * 8);
            float2 a13 = *(float2*)(smem + SM_A + (r0 + 8) * 512 + phys * 8);
            a[mt][0] = __float_as_uint(a02.x);
            a[mt][1] = __float_as_uint(a13.x);
            a[mt][2] = __float_as_uint(a02.y);
            a[mt][3] = __float_as_uint(a13.y);
        }
#pragma unroll
        for (int nt = 0; nt < 4; nt++) {
            int n0 = wn + 8 * nt + g;
            float2 b01 = *(float2*)(smem + SM_B + n0 * 512 + phys * 8);
            bfr[nt][0] = __float_as_uint(b01.x);
            bfr[nt][1] = __float_as_uint(b01.y);
        }
#pragma unroll
        for (int mt = 0; mt < 2; mt++)
#pragma unroll
            for (int nt = 0; nt < 4; nt++) {
                asm volatile(
                    "mma.sync.aligned.m16n8k8.row.col.f32.tf32.tf32.f32 "
                    "{%0,%1,%2,%3}, {%4,%5,%6,%7}, {%8,%9}, {%0,%1,%2,%3};"
                    : "+f"(acc[mt][nt][0]), "+f"(acc[mt][nt][1]),
                      "+f"(acc[mt][nt][2]), "+f"(acc[mt][nt][3])
                    : "r"(a[mt][0]), "r"(a[mt][1]), "r"(a[mt][2]), "r"(a[mt][3]),
                      "r"(bfr[nt][0]), "r"(bfr[nt][1]));
            }
    }

    // ---- epilogue: d = sqrt(max(sqi + sqj - 2*dot, 0) + eps) ----
    const float* sqi_s = (const float*)(smem + SM_SQI);
    const float* sqj_s = (const float*)(smem + SM_SQJ);
    float2 sqj2[4];
#pragma unroll
    for (int nt = 0; nt < 4; nt++)
        sqj2[nt] = *(const float2*)&sqj_s[wn + 8 * nt + 2 * cc];

#pragma unroll
    for (int mt = 0; mt < 2; mt++) {
#pragma unroll
        for (int h = 0; h < 2; h++) {
            int row = wm + 16 * mt + 8 * h + g;
            float si = sqi_s[row];
            float* orow = out + ((size_t)(b * N_ + i0 + row)) * N_ + j0 + wn;
#pragma unroll
            for (int nt = 0; nt < 4; nt++) {
                float d0 = acc[mt][nt][2 * h];
                float d1 = acc[mt][nt][2 * h + 1];
                float v0 = sqrtf(fmaxf(fmaf(-2.f, d0, si + sqj2[nt].x), 0.f) + 1e-7f);
                float v1 = sqrtf(fmaxf(fmaf(-2.f, d1, si + sqj2[nt].y), 0.f) + 1e-7f);
                *(float2*)(orow + 8 * nt + 2 * cc) = make_float2(v0, v1);
            }
        }
    }
}

extern "C" void kernel_launch(void* const* d_in, const int* in_sizes, int n_in,
                              void* d_out, int out_size) {
    const float* x = (const float*)d_in[0];
    float* out = (float*)d_out;

    sq_kernel<<<(B_ * N_) / 256, 256>>>(x);

    cudaFuncSetAttribute(edm_mma_kernel, cudaFuncAttributeMaxDynamicSharedMemorySize, SM_TOTAL);
    dim3 grid(N_ / TN, N_ / TM, B_);
    edm_mma_kernel<<<grid, 256, SM_TOTAL>>>(x, out);
}

// round 5
// speedup vs baseline: 2.0207x; 2.0207x over previous
#include <cuda_runtime.h>
#include <cstdint>

#define B_  4
#define N_  2048
#define D_  128
#define TM  256
#define TN  128

// smem layout (bytes)
#define SM_SQI 0
#define SM_SQJ 1024
#define SM_A   2048
#define SM_B   (2048 + 131072)
#define SM_TOTAL (2048 + 131072 + 65536)

__device__ float g_sq[B_ * N_];

__global__ void sq_kernel(const float* __restrict__ x) {
    int r = blockIdx.x * blockDim.x + threadIdx.x;
    const float4* p = (const float4*)(x + (size_t)r * D_);
    float s = 0.f;
#pragma unroll
    for (int t = 0; t < D_ / 4; t++) {
        float4 v = p[t];
        s += v.x * v.x + v.y * v.y + v.z * v.z + v.w * v.w;
    }
    g_sq[r] = s;
}

__global__ __launch_bounds__(512, 1) void edm_mma_kernel(const float* __restrict__ x,
                                                         float* __restrict__ out) {
    extern __shared__ char smem[];
    const int tid = threadIdx.x;
    const int wid = tid >> 5;
    const int lane = tid & 31;
    const int g  = lane >> 2;   // 0..7
    const int cc = lane & 3;    // 0..3

    const int b  = blockIdx.z;
    const int i0 = blockIdx.y * TM;
    const int j0 = blockIdx.x * TN;
    const float* xb = x + (size_t)b * N_ * D_;

    // ---- load phase: pair-interleaved, XOR-swizzled smem tiles ----
    // slot s = 4*kbi + c holds (x[8*kbi+c], x[8*kbi+c+4]); phys = s ^ ((r&3)<<2)
    {
        const int bb = tid & 3;          // -> r low bits
        const int aa = (tid >> 2) & 3;   // -> kbi low bits
        const int rmid = (tid >> 4);     // 0..31
        // A tile: 256 rows, 8 iters
#pragma unroll
        for (int iter = 0; iter < 8; iter++) {
            int kbi = aa | ((iter & 3) << 2);                 // 0..15
            int r   = bb | (rmid << 2) | ((iter >> 2) << 7);  // 0..255
            const float4* pA = (const float4*)(xb + (size_t)(i0 + r) * D_ + kbi * 8);
            float4 v0 = pA[0], v1 = pA[1];
            float va[8] = {v0.x, v0.y, v0.z, v0.w, v1.x, v1.y, v1.z, v1.w};
            char* rowA = smem + SM_A + r * 512;
            int x4 = (r & 3) << 2;
#pragma unroll
            for (int j = 0; j < 4; j++) {
                int c = (bb + j) & 3;
                int phys = (4 * kbi + c) ^ x4;
                *(float2*)(rowA + phys * 8) = make_float2(va[c], va[c + 4]);
            }
        }
        // B tile: 128 rows, 4 iters
#pragma unroll
        for (int iter = 0; iter < 4; iter++) {
            int kbi = aa | (iter << 2);        // 0..15
            int r   = bb | (rmid << 2);        // 0..127
            const float4* pB = (const float4*)(xb + (size_t)(j0 + r) * D_ + kbi * 8);
            float4 w0 = pB[0], w1 = pB[1];
            float wa[8] = {w0.x, w0.y, w0.z, w0.w, w1.x, w1.y, w1.z, w1.w};
            char* rowB = smem + SM_B + r * 512;
            int x4 = (r & 3) << 2;
#pragma unroll
            for (int j = 0; j < 4; j++) {
                int c = (bb + j) & 3;
                int phys = (4 * kbi + c) ^ x4;
                *(float2*)(rowB + phys * 8) = make_float2(wa[c], wa[c + 4]);
            }
        }
        if (tid < 256)      ((float*)(smem + SM_SQI))[tid]       = g_sq[b * N_ + i0 + tid];
        else if (tid < 384) ((float*)(smem + SM_SQJ))[tid - 256] = g_sq[b * N_ + j0 + tid - 256];
    }
    __syncthreads();

    // ---- mainloop: warp tile 64x32, m16n8k8 tf32 ----
    const int wm = (wid & 3) * 64;    // 0,64,128,192
    const int wn = (wid >> 2) * 32;   // 0,32,64,96

    float acc[4][4][4];
#pragma unroll
    for (int mt = 0; mt < 4; mt++)
#pragma unroll
        for (int nt = 0; nt < 4; nt++)
#pragma unroll
            for (int e = 0; e < 4; e++) acc[mt][nt][e] = 0.f;

    const int gx4 = (g & 3) << 2;
#pragma unroll
    for (int kst = 0; kst < 16; kst++) {
        const int phys = (4 * kst + cc) ^ gx4;
        uint32_t a[4][4], bfr[4][2];
#pragma unroll
        for (int mt = 0; mt < 4; mt++) {
            int r0 = wm + 16 * mt + g;
            float2 a02 = *(float2*)(smem + SM_A + r0 * 512 + phys * 8);
            float2 a13 = *(float2*)(smem + SM_A + (r0 + 8) * 512 + phys * 8);
            a[mt][0] = __float_as_uint(a02.x);
            a[mt][1] = __float_as_uint(a13.x);
            a[mt][2] = __float_as_uint(a02.y);
            a[mt][3] = __float_as_uint(a13.y);
        }
#pragma unroll
        for (int nt = 0; nt < 4; nt++) {
            int n0 = wn + 8 * nt + g;
            float2 b01 = *(float2*)(smem + SM_B + n0 * 512 + phys * 8);
            bfr[nt][0] = __float_as_uint(b01.x);
            bfr[nt][1] = __float_as_uint(b01.y);
        }
#pragma unroll
        for (int mt = 0; mt < 4; mt++)
#pragma unroll
            for (int nt = 0; nt < 4; nt++) {
                asm volatile(
                    "mma.sync.aligned.m16n8k8.row.col.f32.tf32.tf32.f32 "
                    "{%0,%1,%2,%3}, {%4,%5,%6,%7}, {%8,%9}, {%0,%1,%2,%3};"
                    : "+f"(acc[mt][nt][0]), "+f"(acc[mt][nt][1]),
                      "+f"(acc[mt][nt][2]), "+f"(acc[mt][nt][3])
                    : "r"(a[mt][0]), "r"(a[mt][1]), "r"(a[mt][2]), "r"(a[mt][3]),
                      "r"(bfr[nt][0]), "r"(bfr[nt][1]));
            }
    }

    // ---- epilogue: d = sqrt(max(sqi + sqj - 2*dot, 0) + eps) ----
    const float* sqi_s = (const float*)(smem + SM_SQI);
    const float* sqj_s = (const float*)(smem + SM_SQJ);
    float2 sqj2[4];
#pragma unroll
    for (int nt = 0; nt < 4; nt++)
        sqj2[nt] = *(const float2*)&sqj_s[wn + 8 * nt + 2 * cc];

#pragma unroll
    for (int mt = 0; mt < 4; mt++) {
#pragma unroll
        for (int h = 0; h < 2; h++) {
            int row = wm + 16 * mt + 8 * h + g;
            float si = sqi_s[row];
            float* orow = out + ((size_t)(b * N_ + i0 + row)) * N_ + j0 + wn;
#pragma unroll
            for (int nt = 0; nt < 4; nt++) {
                float d0 = acc[mt][nt][2 * h];
                float d1 = acc[mt][nt][2 * h + 1];
                float v0 = sqrtf(fmaxf(fmaf(-2.f, d0, si + sqj2[nt].x), 0.f) + 1e-7f);
                float v1 = sqrtf(fmaxf(fmaf(-2.f, d1, si + sqj2[nt].y), 0.f) + 1e-7f);
                *(float2*)(orow + 8 * nt + 2 * cc) = make_float2(v0, v1);
            }
        }
    }
}

extern "C" void kernel_launch(void* const* d_in, const int* in_sizes, int n_in,
                              void* d_out, int out_size) {
    const float* x = (const float*)d_in[0];
    float* out = (float*)d_out;

    sq_kernel<<<(B_ * N_) / 256, 256>>>(x);

    cudaFuncSetAttribute(edm_mma_kernel, cudaFuncAttributeMaxDynamicSharedMemorySize, SM_TOTAL);
    dim3 grid(N_ / TN, N_ / TM, B_);
    edm_mma_kernel<<<grid, 512, SM_TOTAL>>>(x, out);
}

// round 6
// speedup vs baseline: 2.7918x; 1.3816x over previous
#include <cuda_runtime.h>
#include <cstdint>

#define B_  4
#define N_  2048
#define D_  128

// smem layout (bytes)
#define SM_SQI 0
#define SM_SQJ 512
#define SM_A   8192
#define SM_B0  (8192 + 65536)
#define SM_B1  (8192 + 2 * 65536)
#define SM_TOTAL (8192 + 3 * 65536)

__device__ float g_sq[B_ * N_];

// warp-per-row squared norms
__global__ void sq_kernel(const float* __restrict__ x) {
    int wid = threadIdx.x >> 5, lane = threadIdx.x & 31;
    int row = blockIdx.x * 8 + wid;
    float4 v = *(const float4*)(x + (size_t)row * D_ + lane * 4);
    float s = v.x * v.x + v.y * v.y + v.z * v.z + v.w * v.w;
#pragma unroll
    for (int o = 16; o > 0; o >>= 1) s += __shfl_xor_sync(0xffffffffu, s, o);
    if (lane == 0) g_sq[row] = s;
}

__device__ __forceinline__ float fsqrt_approx(float a) {
    float r;
    asm("sqrt.approx.f32 %0, %1;" : "=f"(r) : "f"(a));
    return r;
}

// convert one 128-row x 128-col fp32 tile into pair-interleaved swizzled smem
// slot s = 4*kbi + c holds (x[8*kbi+c], x[8*kbi+c+4]); phys = s ^ ((r&3)<<2)
__device__ __forceinline__ void load_tile(const float* __restrict__ gbase,
                                          char* __restrict__ sbase, int tid) {
    const int bb = tid & 3;
    const int aa = (tid >> 2) & 3;
    const int rmid = tid >> 4;               // 0..31
    const int r = bb | (rmid << 2);          // 0..127
    const int x4 = (r & 3) << 2;
    char* rowS = sbase + r * 512;
    const float* rowG = gbase + (size_t)r * D_;
#pragma unroll
    for (int iter = 0; iter < 4; iter++) {
        int kbi = aa | (iter << 2);          // 0..15
        float4 v0 = *(const float4*)(rowG + kbi * 8);
        float4 v1 = *(const float4*)(rowG + kbi * 8 + 4);
        float va[8] = {v0.x, v0.y, v0.z, v0.w, v1.x, v1.y, v1.z, v1.w};
#pragma unroll
        for (int j = 0; j < 4; j++) {
            int c = (bb + j) & 3;
            int phys = (4 * kbi + c) ^ x4;
            *(float2*)(rowS + phys * 8) = make_float2(va[c], va[c + 4]);
        }
    }
}

__global__ __launch_bounds__(512) void edm_mma_kernel(const float* __restrict__ x,
                                                      float* __restrict__ out) {
    extern __shared__ char smem[];
    const int tid = threadIdx.x;
    const int wid = tid >> 5;
    const int lane = tid & 31;
    const int g  = lane >> 2;   // 0..7
    const int cc = lane & 3;    // 0..3

    const int half = blockIdx.x;             // 0..1
    const int i0   = blockIdx.y * 128;
    const int b    = blockIdx.z;
    const int jbase = half * 1024;
    const float* xb = x + (size_t)b * N_ * D_;

    // ---- prologue: A slab + B tile 0 + norms ----
    load_tile(xb + (size_t)i0 * D_, smem + SM_A, tid);
    load_tile(xb + (size_t)jbase * D_, smem + SM_B0, tid);
    if (tid < 128) ((float*)(smem + SM_SQI))[tid] = g_sq[b * N_ + i0 + tid];
    ((float*)(smem + SM_SQJ))[tid]       = g_sq[b * N_ + jbase + tid];
    ((float*)(smem + SM_SQJ))[tid + 512] = g_sq[b * N_ + jbase + tid + 512];
    __syncthreads();

    const int wm = (wid & 3) * 32;    // 0,32,64,96
    const int wn = (wid >> 2) * 32;   // 0,32,64,96
    const int gx4 = (g & 3) << 2;
    const float* sqi_s = (const float*)(smem + SM_SQI);
    const float* sqj_s = (const float*)(smem + SM_SQJ);

    // prefetch mapping (matches load_tile)
    const int bb = tid & 3;
    const int aa = (tid >> 2) & 3;
    const int pr = bb | ((tid >> 4) << 2);   // 0..127
    const int px4 = (pr & 3) << 2;

#pragma unroll 1
    for (int jj = 0; jj < 8; jj++) {
        char* bufC = smem + (jj & 1 ? SM_B1 : SM_B0);
        char* bufN = smem + (jj & 1 ? SM_B0 : SM_B1);

        // ---- mainloop: warp tile 32x32, m16n8k8 tf32 ----
        float acc[2][4][4];
#pragma unroll
        for (int mt = 0; mt < 2; mt++)
#pragma unroll
            for (int nt = 0; nt < 4; nt++)
#pragma unroll
                for (int e = 0; e < 4; e++) acc[mt][nt][e] = 0.f;

#pragma unroll
        for (int kst = 0; kst < 16; kst++) {
            const int phys = (4 * kst + cc) ^ gx4;
            uint32_t a[2][4], bfr[4][2];
#pragma unroll
            for (int mt = 0; mt < 2; mt++) {
                int r0 = wm + 16 * mt + g;
                float2 a02 = *(float2*)(smem + SM_A + r0 * 512 + phys * 8);
                float2 a13 = *(float2*)(smem + SM_A + (r0 + 8) * 512 + phys * 8);
                a[mt][0] = __float_as_uint(a02.x);
                a[mt][1] = __float_as_uint(a13.x);
                a[mt][2] = __float_as_uint(a02.y);
                a[mt][3] = __float_as_uint(a13.y);
            }
#pragma unroll
            for (int nt = 0; nt < 4; nt++) {
                int n0 = wn + 8 * nt + g;
                float2 b01 = *(float2*)(bufC + n0 * 512 + phys * 8);
                bfr[nt][0] = __float_as_uint(b01.x);
                bfr[nt][1] = __float_as_uint(b01.y);
            }
#pragma unroll
            for (int mt = 0; mt < 2; mt++)
#pragma unroll
                for (int nt = 0; nt < 4; nt++) {
                    asm volatile(
                        "mma.sync.aligned.m16n8k8.row.col.f32.tf32.tf32.f32 "
                        "{%0,%1,%2,%3}, {%4,%5,%6,%7}, {%8,%9}, {%0,%1,%2,%3};"
                        : "+f"(acc[mt][nt][0]), "+f"(acc[mt][nt][1]),
                          "+f"(acc[mt][nt][2]), "+f"(acc[mt][nt][3])
                        : "r"(a[mt][0]), "r"(a[mt][1]), "r"(a[mt][2]), "r"(a[mt][3]),
                          "r"(bfr[nt][0]), "r"(bfr[nt][1]));
                }
        }

        // ---- prefetch next B tile into regs (latency hidden by epilogue) ----
        float4 pf[4][2];
        if (jj < 7) {
            const float* rowG = xb + (size_t)(jbase + (jj + 1) * 128 + pr) * D_;
#pragma unroll
            for (int iter = 0; iter < 4; iter++) {
                int kbi = aa | (iter << 2);
                pf[iter][0] = *(const float4*)(rowG + kbi * 8);
                pf[iter][1] = *(const float4*)(rowG + kbi * 8 + 4);
            }
        }

        // ---- epilogue ----
        {
            float2 sqj2[4];
            const int sjb = jj * 128 + wn;
#pragma unroll
            for (int nt = 0; nt < 4; nt++)
                sqj2[nt] = *(const float2*)&sqj_s[sjb + 8 * nt + 2 * cc];
#pragma unroll
            for (int mt = 0; mt < 2; mt++) {
#pragma unroll
                for (int h = 0; h < 2; h++) {
                    int row = wm + 16 * mt + 8 * h + g;
                    float si = sqi_s[row];
                    float* orow = out + ((size_t)(b * N_ + i0 + row)) * N_ +
                                  jbase + jj * 128 + wn;
#pragma unroll
                    for (int nt = 0; nt < 4; nt++) {
                        float d0 = acc[mt][nt][2 * h];
                        float d1 = acc[mt][nt][2 * h + 1];
                        float v0 = fsqrt_approx(fmaxf(fmaf(-2.f, d0, si + sqj2[nt].x), 0.f) + 1e-7f);
                        float v1 = fsqrt_approx(fmaxf(fmaf(-2.f, d1, si + sqj2[nt].y), 0.f) + 1e-7f);
                        *(float2*)(orow + 8 * nt + 2 * cc) = make_float2(v0, v1);
                    }
                }
            }
        }

        // ---- store prefetched tile into the other buffer ----
        if (jj < 7) {
            char* rowS = bufN + pr * 512;
#pragma unroll
            for (int iter = 0; iter < 4; iter++) {
                int kbi = aa | (iter << 2);
                float va[8] = {pf[iter][0].x, pf[iter][0].y, pf[iter][0].z, pf[iter][0].w,
                               pf[iter][1].x, pf[iter][1].y, pf[iter][1].z, pf[iter][1].w};
#pragma unroll
                for (int j2 = 0; j2 < 4; j2++) {
                    int c = (bb + j2) & 3;
                    int phys = (4 * kbi + c) ^ px4;
                    *(float2*)(rowS + phys * 8) = make_float2(va[c], va[c + 4]);
                }
            }
        }
        __syncthreads();
    }
}

extern "C" void kernel_launch(void* const* d_in, const int* in_sizes, int n_in,
                              void* d_out, int out_size) {
    const float* x = (const float*)d_in[0];
    float* out = (float*)d_out;

    sq_kernel<<<B_ * N_ / 8, 256>>>(x);

    cudaFuncSetAttribute(edm_mma_kernel, cudaFuncAttributeMaxDynamicSharedMemorySize, SM_TOTAL);
    dim3 grid(2, N_ / 128, B_);
    edm_mma_kernel<<<grid, 512, SM_TOTAL>>>(x, out);
}